// round 13
// baseline (speedup 1.0000x reference)
#include <cuda_runtime.h>
#include <cuda_fp16.h>
#include <cstdint>

// ---------------- problem constants ----------------
#define BATCH  16384
#define NFEAT  16
#define MTOT   4844
#define KPAD   4928          // run-padded (84 pads), = 154 * 32
#define KSTAGE 32
#define NSTAGE 154
#define OUTD   256
#define BM     64            // grid 256, 2 CTAs/SM
#define NTHR   256           // 8 warps: 2 (M32) x 4 (N64)
#define EHSTR  162           // fp16 staging row stride (halves, 81 words odd)
#define EDSTR  155           // packed-pair row stride (words, odd -> conflict-free)

// SMEM (bytes): 64B rows, swizzle phys_seg = seg ^ ((row>>1)&3)
#define A_BUFSZ 4096                           // 64 rows x 64B
#define B_BUFSZ 16384                          // 256 rows x 64B
#define A_OFF   0                              // 3 bufs -> 12288
#define B_OFF   (3 * A_BUFSZ)                  // 12288, 3 bufs -> +49152
#define ED_OFF  (B_OFF + 3 * B_BUFSZ)          // 61440; Ed 64*155*4 = 39680
#define SMEM_REQ (ED_OFF + BM * EDSTR * 4)     // 101120 (x2 CTAs = 202240, fits)

// ---------------- device globals ----------------
__device__ __align__(16) __half   g_Wh[OUTD * KPAD];   // fp16 W, permuted K
__device__ __align__(16) uint32_t g_TBLP[KPAD / 2];    // per-PAIR: e1 | (e2<<16)
__device__ int g_KMAP[KPAD];                           // new k -> original m (-1 pad)

__device__ __forceinline__ int pair_rank(int a, int b) {
    return a * 16 - (a * (a - 1)) / 2 + (b - a);
}

// ---- prep 1: run-padded K map + pair table (fast: O(16)/thread + block scan) ----
// Runs (constant e1, consecutive e2): run 0 = deg1+deg2 (e1=0, len 152);
// runs 1..16 = deg3 by a; runs 17..152 = deg4 by pair_rank(a,b). Odd runs pad +1.
__global__ void prep_map() {
    __shared__ int rstart[153];
    __shared__ int rlen[153];
    const int t = threadIdx.x;
    if (t < 153) {
        int len;
        if (t == 0) len = 152;
        else if (t < 17) { int a = t - 1; len = 136 - (a * 16 - a * (a - 1) / 2); }
        else {
            int p = t - 17, r = p, a = 0;
            while (r >= 16 - a) { r -= 16 - a; a++; }
            int b = a + r;
            len = 136 - (b * 16 - b * (b - 1) / 2);
        }
        rlen[t] = len;
    }
    __syncthreads();
    if (t == 0) {
        int acc = 0;
        for (int i = 0; i < 153; ++i) { rstart[i] = acc; acc += (rlen[i] + 1) & ~1; }
    }
    __syncthreads();

    int m = blockIdx.x * blockDim.x + t;
    if (m >= MTOT) return;
    int run, off, len;
    uint32_t e1, e2;
    if (m < 152) {
        run = 0; off = m; e1 = 0; e2 = 1 + m;
    } else if (m < 968) {
        int r = m - 152, a = 0;
        while (true) { int k = 16 - a; int t2 = k * (k + 1) / 2; if (r < t2) break; r -= t2; a++; }
        int praa = a * 16 - a * (a - 1) / 2;
        run = 1 + a; off = r;
        e1 = 1 + a; e2 = 17 + praa + r;
    } else {
        int r = m - 968, a = 0;
        while (true) { int k = 16 - a; int t3 = k * (k + 1) * (k + 2) / 6; if (r < t3) break; r -= t3; a++; }
        int b = a;
        while (true) { int k = 16 - b; int t2 = k * (k + 1) / 2; if (r < t2) break; r -= t2; b++; }
        int prab = pair_rank(a, b);
        int prbb = b * 16 - b * (b - 1) / 2;
        run = 17 + prab; off = r;
        e1 = 17 + prab; e2 = 17 + prbb + r;
    }
    len = rlen[run];
    int k = rstart[run] + off;
    g_KMAP[k] = m;
    if (!(k & 1)) g_TBLP[k >> 1] = e1 | (e2 << 16);
    if (off == len - 1 && (len & 1)) g_KMAP[k + 1] = -1;   // pad slot
}

// ---- prep 2: permuted fp16 W (pads get 0) ----
__global__ void prep_w(const float* __restrict__ W) {
    int idx = blockIdx.x * blockDim.x + threadIdx.x;
    if (idx >= OUTD * KPAD) return;
    int n = idx / KPAD, k = idx - n * KPAD;
    int m = g_KMAP[k];
    float w = (m >= 0) ? W[(size_t)n * MTOT + m] : 0.0f;
    g_Wh[idx] = __float2half_rn(w);
}

// ---------------- PTX helpers ----------------
__device__ __forceinline__ uint32_t smem_u32(const void* p) {
    uint32_t a;
    asm("{ .reg .u64 t; cvta.to.shared.u64 t, %1; cvt.u32.u64 %0, t; }" : "=r"(a) : "l"(p));
    return a;
}
__device__ __forceinline__ void cp_async16(uint32_t dst, const void* src) {
    asm volatile("cp.async.cg.shared.global [%0], [%1], 16;" :: "r"(dst), "l"(src) : "memory");
}
__device__ __forceinline__ void ldsm_x4(uint32_t (&r)[4], uint32_t addr) {
    asm volatile("ldmatrix.sync.aligned.m8n8.x4.shared.b16 {%0,%1,%2,%3}, [%4];"
                 : "=r"(r[0]), "=r"(r[1]), "=r"(r[2]), "=r"(r[3]) : "r"(addr));
}
__device__ __forceinline__ void mma16816(float (&c)[4], const uint32_t (&a)[4],
                                         uint32_t b0, uint32_t b1) {
    asm volatile(
        "mma.sync.aligned.m16n8k16.row.col.f32.f16.f16.f32 "
        "{%0,%1,%2,%3}, {%4,%5,%6,%7}, {%8,%9}, {%0,%1,%2,%3};"
        : "+f"(c[0]), "+f"(c[1]), "+f"(c[2]), "+f"(c[3])
        : "r"(a[0]), "r"(a[1]), "r"(a[2]), "r"(a[3]), "r"(b0), "r"(b1));
}

// ---------------- main fused kernel ----------------
// 256 CTAs x 256 threads (2/SM). CTA tile M=64 x N=256; K staged by 32;
// 3-deep rings, ONE barrier/stage. Pair-packed E: per monomial PAIR,
// 1 LDS.b32 + 1 LDS.b16 + PRMT + HMUL2 (half the gen crossbar traffic).
__global__ void __launch_bounds__(NTHR, 2) taylor_main(
    const float* __restrict__ x,
    const float* __restrict__ bias,
    float* __restrict__ out)
{
    extern __shared__ char smem[];
    const uint32_t sbase = smem_u32(smem);
    uint32_t* Ed = (uint32_t*)(smem + ED_OFF);

    const int tid  = threadIdx.x;
    const int wid  = tid >> 5;
    const int lane = tid & 31;
    const int b0   = blockIdx.x * BM;
    const int wm   = wid & 1;    // M block (32 rows)
    const int wn   = wid >> 1;   // N block (64 cols)

    // ---- prologue: tanh -> fp16 staging -> packed pair table Ed ----
    {
        float*  Tf = (float*)(smem + A_OFF);   // [64][17] fp32 scratch (A ring, dead after)
        __half* Eh = (__half*)(smem + B_OFF);  // [64][162] fp16 staging (B ring, dead after)
        #pragma unroll
        for (int i = 0; i < (BM * NFEAT) / NTHR; ++i) {
            int q = tid + i * NTHR;
            int row = q >> 4, f = q & 15;
            float t = tanhf(x[(size_t)(b0 + row) * NFEAT + f]);
            Tf[row * 17 + f] = t;
            Eh[row * EHSTR + 1 + f] = __float2half_rn(t);
        }
        if (tid < BM) {
            Eh[tid * EHSTR + 0]   = __float2half_rn(1.0f);
            Eh[tid * EHSTR + 153] = __ushort_as_half(0);
            Eh[tid * EHSTR + 154] = __ushort_as_half(0);
        }
        __syncthreads();
        #pragma unroll
        for (int i = 0; i < (136 * BM) / NTHR; ++i) {
            int q = tid + i * NTHR;
            int row = q & 63, p = q >> 6;
            // unrank pair p -> (a,b)
            int r = p, a = 0;
            while (r >= 16 - a) { r -= 16 - a; a++; }
            int b = a + r;
            Eh[row * EHSTR + 17 + p] = __float2half_rn(Tf[row * 17 + a] * Tf[row * 17 + b]);
        }
        __syncthreads();
        // pack adjacent pairs: Ed[row][c] = (Eh[c], Eh[c+1]); c < 154
        {
            const int row = tid & 63;
            const __half* ehr = Eh + row * EHSTR;
            for (int c = tid >> 6; c < 154; c += 4) {
                uint32_t lo = __half_as_ushort(ehr[c]);
                uint32_t hi = __half_as_ushort(ehr[c + 1]);
                Ed[row * EDSTR + c] = lo | (hi << 16);
            }
        }
        __syncthreads();   // Ed ready; Tf/Eh dead
    }

    // ---- gen assignment: row = tid&63, 8 k (4 pairs) per thread ----
    const int grow = tid & 63;
    const int gkb  = (tid >> 6) << 3;      // 0,8,16,24
    const int gsw  = (grow >> 1) & 3;
    const uint32_t edRow  = sbase + ED_OFF + grow * (EDSTR * 4);
    const uint32_t gAaddr = sbase + A_OFF + grow * 64 +
                            (uint32_t)((gkb >> 3) ^ gsw) * 16;

    #define GEN_A(s_, bo_) do {                                                     \
        const int pb = (s_) * 16 + (gkb >> 1);                                      \
        uint32_t tt[4];                                                             \
        *(uint4*)tt = *(const uint4*)&g_TBLP[pb];                                   \
        uint32_t hh[4];                                                             \
        _Pragma("unroll")                                                           \
        for (int q = 0; q < 4; ++q) {                                               \
            uint32_t tq = tt[q];                                                    \
            uint32_t ev, e1v, e1b;                                                  \
            asm("ld.shared.b32 %0, [%1];" : "=r"(ev)  : "r"(edRow + ((tq >> 16) << 2))); \
            asm("ld.shared.u16 %0, [%1];" : "=r"(e1v) : "r"(edRow + ((tq & 0xffffu) << 2))); \
            asm("prmt.b32 %0, %1, %1, 0x1010;" : "=r"(e1b) : "r"(e1v));             \
            asm("mul.rn.f16x2 %0, %1, %2;" : "=r"(hh[q]) : "r"(ev), "r"(e1b));      \
        }                                                                           \
        asm volatile("st.shared.v4.b32 [%0], {%1,%2,%3,%4};"                        \
                     :: "r"(gAaddr + (bo_)), "r"(hh[0]), "r"(hh[1]), "r"(hh[2]), "r"(hh[3]) : "memory"); \
    } while (0)

    // B stage: 256 rows x 4 segs = 1024 chunks = 4/thread (EXACT)
    #define LOAD_B(s_, bo_) do {                                                    \
        _Pragma("unroll")                                                           \
        for (int i = 0; i < 4; ++i) {                                               \
            int c = tid + i * NTHR;                                                 \
            int row = c >> 2, seg = c & 3;                                          \
            const __half* src = g_Wh + (size_t)row * KPAD + (s_) * KSTAGE + seg * 8;\
            cp_async16(sbase + B_OFF + (bo_) + row * 64 +                           \
                       (uint32_t)(seg ^ ((row >> 1) & 3)) * 16, src);               \
        }                                                                           \
        asm volatile("cp.async.commit_group;" ::: "memory");                        \
    } while (0)

    // ---- pipeline prologue: stages 0,1 ----
    GEN_A(0, 0);            LOAD_B(0, 0);
    GEN_A(1, A_BUFSZ);      LOAD_B(1, B_BUFSZ);

    float acc[2][8][4];
    #pragma unroll
    for (int i = 0; i < 2; ++i)
        #pragma unroll
        for (int j = 0; j < 8; ++j)
            #pragma unroll
            for (int q = 0; q < 4; ++q) acc[i][j][q] = 0.0f;

    // ldsm lane addressing: 4 segs/row, phys = seg ^ ((row>>1)&3)
    const int ra   = wm * 32 + (lane & 15);
    const int asw  = (ra >> 1) & 3;
    const int alog = lane >> 4;
    const uint32_t aBase = sbase + A_OFF + ra * 64;

    const int bq    = lane >> 3;
    const int rbrow = wn * 64 + ((bq >> 1) << 3) + (lane & 7);
    const int bsw   = (rbrow >> 1) & 3;
    const int blog  = bq & 1;
    const uint32_t bBase = sbase + B_OFF + rbrow * 64;

    const int kskew = wid & 1;     // warp-skewed traversal
    const int nskew = wid & 3;

    // ---- main loop: ONE barrier per stage, 3-deep ----
    for (int s = 0; s < NSTAGE; ++s) {
        const int buf = s % 3;
        if (s == NSTAGE - 1)
            asm volatile("cp.async.wait_group 0;" ::: "memory");
        else
            asm volatile("cp.async.wait_group 1;" ::: "memory");
        __syncthreads();   // A(s)/B(s) ready; buf (s+2)%3 vacated (readers of s-1 crossed)

        if (s + 2 < NSTAGE) {
            const int nb = (s + 2) % 3;
            LOAD_B(s + 2, nb * B_BUFSZ);
            GEN_A(s + 2, nb * A_BUFSZ);    // independent of mma -> overlaps
        }

        const uint32_t aB = aBase + buf * A_BUFSZ;
        const uint32_t bB = bBase + buf * B_BUFSZ;
        #pragma unroll
        for (int kf0 = 0; kf0 < 2; ++kf0) {
            const int kf = kf0 ^ kskew;
            uint32_t a[2][4];
            const uint32_t aoff = (uint32_t)((alog + 2 * kf) ^ asw) * 16;
            ldsm_x4(a[0], aB + aoff);
            ldsm_x4(a[1], aB + aoff + 16 * 64);
            const uint32_t boff = (uint32_t)((blog + 2 * kf) ^ bsw) * 16;
            #pragma unroll
            for (int nb0 = 0; nb0 < 4; ++nb0) {
                const int nb2 = (nb0 + nskew) & 3;
                uint32_t b[4];
                ldsm_x4(b, bB + nb2 * (16 * 64) + boff);
                mma16816(acc[0][nb2 * 2 + 0], a[0], b[0], b[1]);
                mma16816(acc[0][nb2 * 2 + 1], a[0], b[2], b[3]);
                mma16816(acc[1][nb2 * 2 + 0], a[1], b[0], b[1]);
                mma16816(acc[1][nb2 * 2 + 1], a[1], b[2], b[3]);
            }
        }
    }

    // ---- epilogue: bias + relu + store ----
    {
        const int rbase = b0 + wm * 32 + (lane >> 2);
        const int cbase = wn * 64 + (lane & 3) * 2;
        #pragma unroll
        for (int mf = 0; mf < 2; ++mf) {
            #pragma unroll
            for (int nf = 0; nf < 8; ++nf) {
                const int col = cbase + nf * 8;
                const float bz0 = __ldg(&bias[col]);
                const float bz1 = __ldg(&bias[col + 1]);
                const int r0 = rbase + mf * 16;
                float2 v0, v1;
                v0.x = fmaxf(acc[mf][nf][0] + bz0, 0.0f);
                v0.y = fmaxf(acc[mf][nf][1] + bz1, 0.0f);
                v1.x = fmaxf(acc[mf][nf][2] + bz0, 0.0f);
                v1.y = fmaxf(acc[mf][nf][3] + bz1, 0.0f);
                *reinterpret_cast<float2*>(out + (size_t)r0 * OUTD + col)       = v0;
                *reinterpret_cast<float2*>(out + (size_t)(r0 + 8) * OUTD + col) = v1;
            }
        }
    }
    #undef GEN_A
    #undef LOAD_B
}

// ---------------- launch ----------------
extern "C" void kernel_launch(void* const* d_in, const int* in_sizes, int n_in,
                              void* d_out, int out_size) {
    const float* x = (const float*)d_in[0];
    const float* W = (const float*)d_in[1];
    const float* b = (const float*)d_in[2];
    float* out = (float*)d_out;

    cudaFuncSetAttribute(taylor_main, cudaFuncAttributeMaxDynamicSharedMemorySize, SMEM_REQ);

    prep_map<<<(MTOT + 255) / 256, 256>>>();
    prep_w<<<(OUTD * KPAD + 255) / 256, 256>>>(W);
    taylor_main<<<BATCH / BM, NTHR, SMEM_REQ>>>(x, b, out);
}

// round 14
// speedup vs baseline: 6.7705x; 6.7705x over previous
#include <cuda_runtime.h>
#include <cuda_fp16.h>
#include <cstdint>

// ---------------- problem constants ----------------
#define BATCH  16384
#define NFEAT  16
#define MTOT   4844
#define KPAD   4928          // run-padded (84 pads), = 154 * 32
#define KSTAGE 32
#define NSTAGE 154
#define OUTD   256
#define BM     64            // grid 256, 2 CTAs/SM
#define NTHR   256           // 8 warps: 2 (M32) x 4 (N64)
#define EHSTR  162           // fp16 staging row stride (halves)
#define EDSTR  155           // packed-pair row stride (words, odd -> conflict-free)

// SMEM (bytes): 64B rows, swizzle phys_seg = seg ^ ((row>>1)&3)
#define A_BUFSZ 4096                           // 64 rows x 64B
#define B_BUFSZ 16384                          // 256 rows x 64B
#define A_OFF   0                              // 3 bufs -> 12288
#define B_OFF   (3 * A_BUFSZ)                  // 12288, 3 bufs -> +49152
#define ED_OFF  (B_OFF + 3 * B_BUFSZ)          // 61440; Ed 64*155*4 = 39680
#define SMEM_REQ (ED_OFF + BM * EDSTR * 4)     // 101120 (x2 CTAs fits)

// ---------------- device globals ----------------
__device__ __align__(16) __half   g_Wh[OUTD * KPAD];   // fp16 W, permuted K
__device__ __align__(16) uint32_t g_TBLP[KPAD / 2];    // per-PAIR: e1 | (e2<<16)
__device__ int g_KMAP[KPAD];                           // new k -> original m (-1 pad)

__device__ __forceinline__ int pair_rank(int a, int b) {
    return a * 16 - (a * (a - 1)) / 2 + (b - a);
}

// ---- prep 1: run-padded K map + pair table ----
__global__ void prep_map() {
    __shared__ int rstart[153];
    __shared__ int rlen[153];
    const int t = threadIdx.x;
    if (t < 153) {
        int len;
        if (t == 0) len = 152;
        else if (t < 17) { int a = t - 1; len = 136 - (a * 16 - a * (a - 1) / 2); }
        else {
            int p = t - 17, r = p, a = 0;
            while (r >= 16 - a) { r -= 16 - a; a++; }
            int b = a + r;
            len = 136 - (b * 16 - b * (b - 1) / 2);
        }
        rlen[t] = len;
    }
    __syncthreads();
    if (t == 0) {
        int acc = 0;
        for (int i = 0; i < 153; ++i) { rstart[i] = acc; acc += (rlen[i] + 1) & ~1; }
    }
    __syncthreads();

    int m = blockIdx.x * blockDim.x + t;
    if (m >= MTOT) return;
    int run, off, len;
    uint32_t e1, e2;
    if (m < 152) {
        run = 0; off = m; e1 = 0; e2 = 1 + m;
    } else if (m < 968) {
        int r = m - 152, a = 0;
        while (true) { int k = 16 - a; int t2 = k * (k + 1) / 2; if (r < t2) break; r -= t2; a++; }
        int praa = a * 16 - a * (a - 1) / 2;
        run = 1 + a; off = r;
        e1 = 1 + a; e2 = 17 + praa + r;
    } else {
        int r = m - 968, a = 0;
        while (true) { int k = 16 - a; int t3 = k * (k + 1) * (k + 2) / 6; if (r < t3) break; r -= t3; a++; }
        int b = a;
        while (true) { int k = 16 - b; int t2 = k * (k + 1) / 2; if (r < t2) break; r -= t2; b++; }
        int prab = pair_rank(a, b);
        int prbb = b * 16 - b * (b - 1) / 2;
        run = 17 + prab; off = r;
        e1 = 17 + prab; e2 = 17 + prbb + r;
    }
    len = rlen[run];
    int k = rstart[run] + off;
    g_KMAP[k] = m;
    if (!(k & 1)) g_TBLP[k >> 1] = e1 | (e2 << 16);
    if (off == len - 1 && (len & 1)) g_KMAP[k + 1] = -1;   // pad slot
}

// ---- prep 2: permuted fp16 W (pads get 0) ----
__global__ void prep_w(const float* __restrict__ W) {
    int idx = blockIdx.x * blockDim.x + threadIdx.x;
    if (idx >= OUTD * KPAD) return;
    int n = idx / KPAD, k = idx - n * KPAD;
    int m = g_KMAP[k];
    float w = (m >= 0) ? W[(size_t)n * MTOT + m] : 0.0f;
    g_Wh[idx] = __float2half_rn(w);
}

// ---------------- PTX helpers ----------------
__device__ __forceinline__ uint32_t smem_u32(const void* p) {
    uint32_t a;
    asm("{ .reg .u64 t; cvta.to.shared.u64 t, %1; cvt.u32.u64 %0, t; }" : "=r"(a) : "l"(p));
    return a;
}
__device__ __forceinline__ void cp_async16(uint32_t dst, const void* src) {
    asm volatile("cp.async.cg.shared.global [%0], [%1], 16;" :: "r"(dst), "l"(src) : "memory");
}
__device__ __forceinline__ void ldsm_x4(uint32_t (&r)[4], uint32_t addr) {
    asm volatile("ldmatrix.sync.aligned.m8n8.x4.shared.b16 {%0,%1,%2,%3}, [%4];"
                 : "=r"(r[0]), "=r"(r[1]), "=r"(r[2]), "=r"(r[3]) : "r"(addr));
}
__device__ __forceinline__ void mma16816(float (&c)[4], const uint32_t (&a)[4],
                                         uint32_t b0, uint32_t b1) {
    asm volatile(
        "mma.sync.aligned.m16n8k16.row.col.f32.f16.f16.f32 "
        "{%0,%1,%2,%3}, {%4,%5,%6,%7}, {%8,%9}, {%0,%1,%2,%3};"
        : "+f"(c[0]), "+f"(c[1]), "+f"(c[2]), "+f"(c[3])
        : "r"(a[0]), "r"(a[1]), "r"(a[2]), "r"(a[3]), "r"(b0), "r"(b1));
}

// ---------------- main fused kernel ----------------
// 256 CTAs x 256 threads (2/SM). CTA tile M=64 x N=256; K staged by 32;
// 3-deep rings, ONE barrier/stage. Pair-packed E generation.
// All loop indices compile-time -> acc stays in registers (R13 fix).
__global__ void __launch_bounds__(NTHR, 2) taylor_main(
    const float* __restrict__ x,
    const float* __restrict__ bias,
    float* __restrict__ out)
{
    extern __shared__ char smem[];
    const uint32_t sbase = smem_u32(smem);
    uint32_t* Ed = (uint32_t*)(smem + ED_OFF);

    const int tid  = threadIdx.x;
    const int wid  = tid >> 5;
    const int lane = tid & 31;
    const int b0   = blockIdx.x * BM;
    const int wm   = wid & 1;    // M block (32 rows)
    const int wn   = wid >> 1;   // N block (64 cols)

    // ---- prologue: tanh -> fp16 staging -> packed pair table Ed ----
    {
        float*  Tf = (float*)(smem + A_OFF);   // [64][17] fp32 scratch
        __half* Eh = (__half*)(smem + B_OFF);  // [64][162] fp16 staging
        #pragma unroll
        for (int i = 0; i < (BM * NFEAT) / NTHR; ++i) {
            int q = tid + i * NTHR;
            int row = q >> 4, f = q & 15;
            float t = tanhf(x[(size_t)(b0 + row) * NFEAT + f]);
            Tf[row * 17 + f] = t;
            Eh[row * EHSTR + 1 + f] = __float2half_rn(t);
        }
        if (tid < BM) {
            Eh[tid * EHSTR + 0]   = __float2half_rn(1.0f);
            Eh[tid * EHSTR + 153] = __ushort_as_half(0);
            Eh[tid * EHSTR + 154] = __ushort_as_half(0);
        }
        __syncthreads();
        #pragma unroll
        for (int i = 0; i < (136 * BM) / NTHR; ++i) {
            int q = tid + i * NTHR;
            int row = q & 63, p = q >> 6;
            int r = p, a = 0;
            while (r >= 16 - a) { r -= 16 - a; a++; }
            int b = a + r;
            Eh[row * EHSTR + 17 + p] = __float2half_rn(Tf[row * 17 + a] * Tf[row * 17 + b]);
        }
        __syncthreads();
        {
            const int row = tid & 63;
            const __half* ehr = Eh + row * EHSTR;
            for (int c = tid >> 6; c < 154; c += 4) {
                uint32_t lo = __half_as_ushort(ehr[c]);
                uint32_t hi = __half_as_ushort(ehr[c + 1]);
                Ed[row * EDSTR + c] = lo | (hi << 16);
            }
        }
        __syncthreads();   // Ed ready; Tf/Eh dead
    }

    // ---- gen assignment: row = tid&63, 8 k (4 pairs) per thread ----
    const int grow = tid & 63;
    const int gkb  = (tid >> 6) << 3;      // 0,8,16,24
    const int gsw  = (grow >> 1) & 3;
    const uint32_t edRow  = sbase + ED_OFF + grow * (EDSTR * 4);
    const uint32_t gAaddr = sbase + A_OFF + grow * 64 +
                            (uint32_t)((gkb >> 3) ^ gsw) * 16;

    #define GEN_A(s_, bo_) do {                                                     \
        const int pb = (s_) * 16 + (gkb >> 1);                                      \
        uint32_t tt[4];                                                             \
        *(uint4*)tt = *(const uint4*)&g_TBLP[pb];                                   \
        uint32_t hh[4];                                                             \
        _Pragma("unroll")                                                           \
        for (int q = 0; q < 4; ++q) {                                               \
            uint32_t tq = tt[q];                                                    \
            uint32_t ev, e1v, e1b;                                                  \
            asm("ld.shared.b32 %0, [%1];" : "=r"(ev)  : "r"(edRow + ((tq >> 16) << 2))); \
            asm("ld.shared.u16 %0, [%1];" : "=r"(e1v) : "r"(edRow + ((tq & 0xffffu) << 2))); \
            asm("prmt.b32 %0, %1, %1, 0x1010;" : "=r"(e1b) : "r"(e1v));             \
            asm("mul.rn.f16x2 %0, %1, %2;" : "=r"(hh[q]) : "r"(ev), "r"(e1b));      \
        }                                                                           \
        asm volatile("st.shared.v4.b32 [%0], {%1,%2,%3,%4};"                        \
                     :: "r"(gAaddr + (bo_)), "r"(hh[0]), "r"(hh[1]), "r"(hh[2]), "r"(hh[3]) : "memory"); \
    } while (0)

    #define LOAD_B(s_, bo_) do {                                                    \
        _Pragma("unroll")                                                           \
        for (int i = 0; i < 4; ++i) {                                               \
            int c = tid + i * NTHR;                                                 \
            int row = c >> 2, seg = c & 3;                                          \
            const __half* src = g_Wh + (size_t)row * KPAD + (s_) * KSTAGE + seg * 8;\
            cp_async16(sbase + B_OFF + (bo_) + row * 64 +                           \
                       (uint32_t)(seg ^ ((row >> 1) & 3)) * 16, src);               \
        }                                                                           \
        asm volatile("cp.async.commit_group;" ::: "memory");                        \
    } while (0)

    // ---- pipeline prologue: stages 0,1 ----
    GEN_A(0, 0);            LOAD_B(0, 0);
    GEN_A(1, A_BUFSZ);      LOAD_B(1, B_BUFSZ);

    float acc[2][8][4];
    #pragma unroll
    for (int i = 0; i < 2; ++i)
        #pragma unroll
        for (int j = 0; j < 8; ++j)
            #pragma unroll
            for (int q = 0; q < 4; ++q) acc[i][j][q] = 0.0f;

    const int ra   = wm * 32 + (lane & 15);
    const int asw  = (ra >> 1) & 3;
    const int alog = lane >> 4;
    const uint32_t aBase = sbase + A_OFF + ra * 64;

    const int bq    = lane >> 3;
    const int rbrow = wn * 64 + ((bq >> 1) << 3) + (lane & 7);
    const int bsw   = (rbrow >> 1) & 3;
    const int blog  = bq & 1;
    const uint32_t bBase = sbase + B_OFF + rbrow * 64;

    // ---- main loop: ONE barrier per stage, 3-deep ----
    for (int s = 0; s < NSTAGE; ++s) {
        const int buf = s % 3;
        if (s == NSTAGE - 1)
            asm volatile("cp.async.wait_group 0;" ::: "memory");
        else
            asm volatile("cp.async.wait_group 1;" ::: "memory");
        __syncthreads();   // A(s)/B(s) ready; buf (s+2)%3 vacated

        if (s + 2 < NSTAGE) {
            const int nb = (s + 2) % 3;
            LOAD_B(s + 2, nb * B_BUFSZ);
            GEN_A(s + 2, nb * A_BUFSZ);    // independent of mma -> overlaps
        }

        const uint32_t aB = aBase + buf * A_BUFSZ;
        const uint32_t bB = bBase + buf * B_BUFSZ;
        #pragma unroll
        for (int kf = 0; kf < 2; ++kf) {
            uint32_t a[2][4];
            const uint32_t aoff = (uint32_t)((alog + 2 * kf) ^ asw) * 16;
            ldsm_x4(a[0], aB + aoff);
            ldsm_x4(a[1], aB + aoff + 16 * 64);
            const uint32_t boff = (uint32_t)((blog + 2 * kf) ^ bsw) * 16;
            #pragma unroll
            for (int nb2 = 0; nb2 < 4; ++nb2) {
                uint32_t b[4];
                ldsm_x4(b, bB + nb2 * (16 * 64) + boff);
                mma16816(acc[0][nb2 * 2 + 0], a[0], b[0], b[1]);
                mma16816(acc[0][nb2 * 2 + 1], a[0], b[2], b[3]);
                mma16816(acc[1][nb2 * 2 + 0], a[1], b[0], b[1]);
                mma16816(acc[1][nb2 * 2 + 1], a[1], b[2], b[3]);
            }
        }
    }

    // ---- epilogue: bias + relu + store ----
    {
        const int rbase = b0 + wm * 32 + (lane >> 2);
        const int cbase = wn * 64 + (lane & 3) * 2;
        #pragma unroll
        for (int mf = 0; mf < 2; ++mf) {
            #pragma unroll
            for (int nf = 0; nf < 8; ++nf) {
                const int col = cbase + nf * 8;
                const float bz0 = __ldg(&bias[col]);
                const float bz1 = __ldg(&bias[col + 1]);
                const int r0 = rbase + mf * 16;
                float2 v0, v1;
                v0.x = fmaxf(acc[mf][nf][0] + bz0, 0.0f);
                v0.y = fmaxf(acc[mf][nf][1] + bz1, 0.0f);
                v1.x = fmaxf(acc[mf][nf][2] + bz0, 0.0f);
                v1.y = fmaxf(acc[mf][nf][3] + bz1, 0.0f);
                *reinterpret_cast<float2*>(out + (size_t)r0 * OUTD + col)       = v0;
                *reinterpret_cast<float2*>(out + (size_t)(r0 + 8) * OUTD + col) = v1;
            }
        }
    }
    #undef GEN_A
    #undef LOAD_B
}

// ---------------- launch ----------------
extern "C" void kernel_launch(void* const* d_in, const int* in_sizes, int n_in,
                              void* d_out, int out_size) {
    const float* x = (const float*)d_in[0];
    const float* W = (const float*)d_in[1];
    const float* b = (const float*)d_in[2];
    float* out = (float*)d_out;

    cudaFuncSetAttribute(taylor_main, cudaFuncAttributeMaxDynamicSharedMemorySize, SMEM_REQ);

    prep_map<<<(MTOT + 255) / 256, 256>>>();
    prep_w<<<(OUTD * KPAD + 255) / 256, 256>>>(W);
    taylor_main<<<BATCH / BM, NTHR, SMEM_REQ>>>(x, b, out);
}

// round 15
// speedup vs baseline: 6.8433x; 1.0107x over previous
#include <cuda_runtime.h>
#include <cuda_fp16.h>
#include <cstdint>

// ---------------- problem constants ----------------
#define BATCH  16384
#define NFEAT  16
#define MTOT   4844
#define KPAD   4864          // pad monomial = 1, pad W = 0
#define KSTAGE 64
#define NSTAGE 76
#define OUTD   256
#define BM     64            // grid 256, 2 CTAs/SM
#define NTHR   256           // 8 warps: 2 (M32) x 4 (N64)
#define EHSTR  162           // fp16 E row stride in halves (conflict-free, validated)

// SMEM (bytes): XOR-swizzled 128B rows; A 3-deep, B 2-deep
#define A_BUFSZ 8192                           // 64 x 128B
#define B_BUFSZ 32768                          // 256 x 128B
#define A_OFF   0                              // 3 bufs -> 24576
#define B_OFF   (3 * A_BUFSZ)                  // 24576, 2 bufs -> +65536
#define E_OFF   (B_OFF + 2 * B_BUFSZ)          // 90112, Eh: 64*162*2 = 20736
#define SMEM_REQ (E_OFF + BM * EHSTR * 2)      // 110848 (x2 CTAs = 221696, fits)

// ---------------- device globals ----------------
__device__ __align__(16) __half   g_Wh[OUTD * KPAD];  // fp16 W [N=256][KPAD]
__device__ __align__(16) uint32_t g_TBL[KPAD];        // m -> e1 | (e2<<16)
__device__ uint32_t g_PAIRT[136];

__device__ __forceinline__ int pair_rank(int a, int b) {
    return a * 16 - (a * (a - 1)) / 2 + (b - a);
}

// Single merged prep launch (validated R9 logic)
__global__ void prep_all(const float* __restrict__ W) {
    int idx = blockIdx.x * blockDim.x + threadIdx.x;
    if (idx < 136) {
        int r = idx, a = 0;
        while (r >= 16 - a) { r -= 16 - a; a++; }
        g_PAIRT[idx] = (uint32_t)a | ((uint32_t)(a + r) << 8);
    }
    if (idx < KPAD) {
        int m = idx;
        uint32_t e1 = 0, e2 = 0;
        if (m < 16) {
            e1 = 1 + m; e2 = 0;
        } else if (m < 152) {
            e1 = 17 + (m - 16); e2 = 0;
        } else if (m < 968) {
            int r = m - 152, a = 0;
            while (true) { int k = 16 - a; int t2 = k * (k + 1) / 2; if (r < t2) break; r -= t2; a++; }
            int b = a;
            while (r >= 16 - b) { r -= 16 - b; b++; }
            int c = b + r;
            e1 = 1 + a; e2 = 17 + pair_rank(b, c);
        } else if (m < MTOT) {
            int r = m - 968, a = 0;
            while (true) { int k = 16 - a; int t3 = k * (k + 1) * (k + 2) / 6; if (r < t3) break; r -= t3; a++; }
            int b = a;
            while (true) { int k = 16 - b; int t2 = k * (k + 1) / 2; if (r < t2) break; r -= t2; b++; }
            int c = b;
            while (r >= 16 - c) { r -= 16 - c; c++; }
            int d = c + r;
            e1 = 17 + pair_rank(a, b); e2 = 17 + pair_rank(c, d);
        } else {
            e1 = 0; e2 = 0;
        }
        g_TBL[m] = e1 | (e2 << 16);
    }
    if (idx < OUTD * KPAD) {
        int n = idx / KPAD, k = idx - n * KPAD;
        float w = (k < MTOT) ? W[(size_t)n * MTOT + k] : 0.0f;
        g_Wh[idx] = __float2half_rn(w);
    }
}

// ---------------- PTX helpers ----------------
__device__ __forceinline__ uint32_t smem_u32(const void* p) {
    uint32_t a;
    asm("{ .reg .u64 t; cvta.to.shared.u64 t, %1; cvt.u32.u64 %0, t; }" : "=r"(a) : "l"(p));
    return a;
}
__device__ __forceinline__ void cp_async16(uint32_t dst, const void* src) {
    asm volatile("cp.async.cg.shared.global [%0], [%1], 16;" :: "r"(dst), "l"(src) : "memory");
}
__device__ __forceinline__ void ldsm_x4(uint32_t (&r)[4], uint32_t addr) {
    asm volatile("ldmatrix.sync.aligned.m8n8.x4.shared.b16 {%0,%1,%2,%3}, [%4];"
                 : "=r"(r[0]), "=r"(r[1]), "=r"(r[2]), "=r"(r[3]) : "r"(addr));
}
__device__ __forceinline__ void mma16816(float (&c)[4], const uint32_t (&a)[4],
                                         uint32_t b0, uint32_t b1) {
    asm volatile(
        "mma.sync.aligned.m16n8k16.row.col.f32.f16.f16.f32 "
        "{%0,%1,%2,%3}, {%4,%5,%6,%7}, {%8,%9}, {%0,%1,%2,%3};"
        : "+f"(c[0]), "+f"(c[1]), "+f"(c[2]), "+f"(c[3])
        : "r"(a[0]), "r"(a[1]), "r"(a[2]), "r"(a[3]), "r"(b0), "r"(b1));
}

// ---------------- main fused kernel ----------------
// 256 CTAs x 256 threads (2/SM). CTA tile M=64 x N=256, K staged by 64.
// ONE barrier per stage. A ring 3-deep (gen prefetch-2), B ring 2-deep
// (cp.async prefetch-1, retired by wait_group 0 before next barrier).
__global__ void __launch_bounds__(NTHR, 2) taylor_main(
    const float* __restrict__ x,
    const float* __restrict__ bias,
    float* __restrict__ out)
{
    extern __shared__ char smem[];
    const uint32_t sbase = smem_u32(smem);
    __half* Eh = (__half*)(smem + E_OFF);

    const int tid  = threadIdx.x;
    const int wid  = tid >> 5;
    const int lane = tid & 31;
    const int b0   = blockIdx.x * BM;
    const int wm   = wid & 1;    // M block (32 rows)
    const int wn   = wid >> 1;   // N block (64 cols)

    // ---- prologue: tanh (fp32 scratch in A ring) -> fp16 E ----
    {
        float* Tf = (float*)(smem + A_OFF);
        #pragma unroll
        for (int i = 0; i < (BM * NFEAT) / NTHR; ++i) {
            int q = tid + i * NTHR;
            int row = q >> 4, f = q & 15;
            float t = tanhf(x[(size_t)(b0 + row) * NFEAT + f]);
            Tf[row * 17 + f] = t;
            Eh[row * EHSTR + 1 + f] = __float2half_rn(t);
        }
        if (tid < BM) Eh[tid * EHSTR] = __float2half_rn(1.0f);
        __syncthreads();
        #pragma unroll
        for (int i = 0; i < (136 * BM) / NTHR; ++i) {
            int q = tid + i * NTHR;
            int row = q & 63, p = q >> 6;
            uint32_t pr = g_PAIRT[p];
            Eh[row * EHSTR + 17 + p] = __float2half_rn(
                Tf[row * 17 + (pr & 255)] * Tf[row * 17 + ((pr >> 8) & 255)]);
        }
        __syncthreads();
    }

    // ---- gen assignment: row = tid&63, 16 k per thread at gkb ----
    const int grow = tid & 63;
    const int gkb  = (tid >> 6) << 4;      // 0,16,32,48
    const int gseg = gkb >> 3;             // 0,2,4,6
    const int grb  = grow & 7;
    const __half* Er = Eh + grow * EHSTR;
    const uint32_t gA0 = sbase + A_OFF + grow * 128 + (uint32_t)((gseg    ) ^ grb) * 16;
    const uint32_t gA1 = sbase + A_OFF + grow * 128 + (uint32_t)((gseg + 1) ^ grb) * 16;

    #define GEN_A(s_, bo_) do {                                                     \
        const int mb = (s_) * KSTAGE + gkb;                                         \
        uint32_t tt[16];                                                            \
        *(uint4*)&tt[0]  = *(const uint4*)&g_TBL[mb];                               \
        *(uint4*)&tt[4]  = *(const uint4*)&g_TBL[mb + 4];                           \
        *(uint4*)&tt[8]  = *(const uint4*)&g_TBL[mb + 8];                           \
        *(uint4*)&tt[12] = *(const uint4*)&g_TBL[mb + 12];                          \
        uint32_t hh[8];                                                             \
        _Pragma("unroll")                                                           \
        for (int q = 0; q < 8; ++q) {                                               \
            uint32_t t0 = tt[2 * q], t1 = tt[2 * q + 1];                            \
            __half p0 = __hmul(Er[t0 & 0xffff], Er[t0 >> 16]);                      \
            __half p1 = __hmul(Er[t1 & 0xffff], Er[t1 >> 16]);                      \
            hh[q] = (uint32_t)__half_as_ushort(p0) |                                \
                    ((uint32_t)__half_as_ushort(p1) << 16);                         \
        }                                                                           \
        asm volatile("st.shared.v4.b32 [%0], {%1,%2,%3,%4};"                        \
                     :: "r"(gA0 + (bo_)), "r"(hh[0]), "r"(hh[1]), "r"(hh[2]), "r"(hh[3]) : "memory"); \
        asm volatile("st.shared.v4.b32 [%0], {%1,%2,%3,%4};"                        \
                     :: "r"(gA1 + (bo_)), "r"(hh[4]), "r"(hh[5]), "r"(hh[6]), "r"(hh[7]) : "memory"); \
    } while (0)

    // B stage: 256 rows x 8 segs = 2048 chunks = 8 per thread (EXACT)
    #define LOAD_B(s_, bo_) do {                                                    \
        _Pragma("unroll")                                                           \
        for (int i = 0; i < 8; ++i) {                                               \
            int c = tid + i * NTHR;                                                 \
            int row = c >> 3, seg = c & 7;                                          \
            const __half* src = g_Wh + (size_t)row * KPAD + (s_) * KSTAGE + seg * 8;\
            cp_async16(sbase + B_OFF + (bo_) + row * 128 +                          \
                       (uint32_t)(seg ^ (row & 7)) * 16, src);                      \
        }                                                                           \
        asm volatile("cp.async.commit_group;" ::: "memory");                        \
    } while (0)

    // ---- pipeline prologue: A for stages 0,1; B for stage 0 ----
    GEN_A(0, 0);
    GEN_A(1, A_BUFSZ);
    LOAD_B(0, 0);

    float acc[2][8][4];
    #pragma unroll
    for (int i = 0; i < 2; ++i)
        #pragma unroll
        for (int j = 0; j < 8; ++j)
            #pragma unroll
            for (int q = 0; q < 4; ++q) acc[i][j][q] = 0.0f;

    // ldsm lane addressing (logical seg -> phys via xor swizzle)
    const int ra   = wm * 32 + (lane & 15);
    const int arb  = ra & 7;
    const int alog = lane >> 4;
    const uint32_t aBase = sbase + A_OFF + ra * 128;

    const int bq    = lane >> 3;
    const int rbrow = wn * 64 + ((bq >> 1) << 3) + (lane & 7);
    const int brb   = rbrow & 7;
    const int blog  = bq & 1;
    const uint32_t bBase = sbase + B_OFF + rbrow * 128;

    // A ring offsets: bufA = s%3, bufA2 = (s+2)%3
    int bufA = 0, bufA2 = 2 * A_BUFSZ;

    // ---- main loop: ONE barrier per stage ----
    for (int s = 0; s < NSTAGE; ++s) {
        asm volatile("cp.async.wait_group 0;" ::: "memory");   // B(s) landed
        __syncthreads();   // A(s)/B(s) visible; all warps done with stage s-1

        if (s + 1 < NSTAGE) LOAD_B(s + 1, ((s + 1) & 1) * B_BUFSZ);  // buf of s-1, vacated
        if (s + 2 < NSTAGE) GEN_A(s + 2, bufA2);                     // A buf of s-1, vacated

        const uint32_t aB = aBase + bufA;
        const uint32_t bB = bBase + (s & 1) * B_BUFSZ;
        #pragma unroll
        for (int kf = 0; kf < 4; ++kf) {
            uint32_t a[2][4];
            const uint32_t aoff = (uint32_t)((alog + 2 * kf) ^ arb) * 16;
            ldsm_x4(a[0], aB + aoff);
            ldsm_x4(a[1], aB + aoff + 16 * 128);
            const uint32_t boff = (uint32_t)((blog + 2 * kf) ^ brb) * 16;
            #pragma unroll
            for (int nb = 0; nb < 4; ++nb) {
                uint32_t b[4];
                ldsm_x4(b, bB + nb * (16 * 128) + boff);
                mma16816(acc[0][nb * 2 + 0], a[0], b[0], b[1]);
                mma16816(acc[0][nb * 2 + 1], a[0], b[2], b[3]);
                mma16816(acc[1][nb * 2 + 0], a[1], b[0], b[1]);
                mma16816(acc[1][nb * 2 + 1], a[1], b[2], b[3]);
            }
        }

        bufA += A_BUFSZ;  if (bufA  == 3 * A_BUFSZ) bufA  = 0;
        bufA2 += A_BUFSZ; if (bufA2 == 3 * A_BUFSZ) bufA2 = 0;
    }

    // ---- epilogue: bias + relu + store ----
    {
        const int rbase = b0 + wm * 32 + (lane >> 2);
        const int cbase = wn * 64 + (lane & 3) * 2;
        #pragma unroll
        for (int mf = 0; mf < 2; ++mf) {
            #pragma unroll
            for (int nf = 0; nf < 8; ++nf) {
                const int col = cbase + nf * 8;
                const float bz0 = __ldg(&bias[col]);
                const float bz1 = __ldg(&bias[col + 1]);
                const int r0 = rbase + mf * 16;
                float2 v0, v1;
                v0.x = fmaxf(acc[mf][nf][0] + bz0, 0.0f);
                v0.y = fmaxf(acc[mf][nf][1] + bz1, 0.0f);
                v1.x = fmaxf(acc[mf][nf][2] + bz0, 0.0f);
                v1.y = fmaxf(acc[mf][nf][3] + bz1, 0.0f);
                *reinterpret_cast<float2*>(out + (size_t)r0 * OUTD + col)       = v0;
                *reinterpret_cast<float2*>(out + (size_t)(r0 + 8) * OUTD + col) = v1;
            }
        }
    }
    #undef GEN_A
    #undef LOAD_B
}

// ---------------- launch ----------------
extern "C" void kernel_launch(void* const* d_in, const int* in_sizes, int n_in,
                              void* d_out, int out_size) {
    const float* x = (const float*)d_in[0];
    const float* W = (const float*)d_in[1];
    const float* b = (const float*)d_in[2];
    float* out = (float*)d_out;

    cudaFuncSetAttribute(taylor_main, cudaFuncAttributeMaxDynamicSharedMemorySize, SMEM_REQ);

    prep_all<<<(OUTD * KPAD + 255) / 256, 256>>>(W);
    taylor_main<<<BATCH / BM, NTHR, SMEM_REQ>>>(x, b, out);
}